// round 16
// baseline (speedup 1.0000x reference)
#include <cuda_runtime.h>
#include <math.h>

#define TOPK 13
#define EPSF 1e-7f
#define MAX_B 64
#define MAX_G 32
#define SCORE_BLOCKS 124
#define FIN_BLOCKS 64

typedef unsigned long long u64;

__device__ float g_facc[MAX_B * 8];           // per-image fg sums (overwritten each launch)
__device__ float g_sacc[SCORE_BLOCKS * 2];    // per-score-block partials (overwritten)

__device__ __forceinline__ float iou_fn(float4 a, float4 b) {
    float x1 = fmaxf(a.x, b.x), y1 = fmaxf(a.y, b.y);
    float x2 = fminf(a.z, b.z), y2 = fminf(a.w, b.w);
    float inter = fmaxf(x2 - x1, 0.0f) * fmaxf(y2 - y1, 0.0f);
    float aa = (a.z - a.x) * (a.w - a.y);
    float ab = (b.z - b.x) * (b.w - b.y);
    return inter / (aa + ab - inter + EPSF);
}

// Blocks [0, B): one block per image — all G gts assigned (warp per gt),
// dedup + per-image accumulation entirely in shared memory.
// Blocks [B, B+SCORE_BLOCKS): dense score reduction, per-block partials.
__global__ __launch_bounds__(256) void k_main(
    const float4* __restrict__ pred_boxes, const float* __restrict__ scores,
    const float2* __restrict__ anchors, const float* __restrict__ strides,
    const float* __restrict__ logits, const float* __restrict__ prompt,
    const float4* __restrict__ gts, const int* __restrict__ img_p,
    int B, int N, int G, int total, int P)
{
    int t = threadIdx.x;
    int lane = t & 31, wid = t >> 5;

    if ((int)blockIdx.x >= B) {
        // ---------------- score role (grid-stride, plain-store partials) ----------------
        int sb = blockIdx.x - B;
        int nv4 = total >> 2;
        float bce = 0.0f, ps = 0.0f;
        for (int i = sb * 256 + t; i < nv4; i += SCORE_BLOCKS * 256) {
            float4 s4 = ((const float4*)scores)[i];
            float sv[4] = {s4.x, s4.y, s4.z, s4.w};
#pragma unroll
            for (int j = 0; j < 4; j++) {
                float s = sv[j];
                float e = __expf(-fabsf(s));
                float pa = 1.0f / (1.0f + e);          // sigmoid(|s|)
                bce += fmaxf(s, 0.0f) - __logf(pa);    // max(s,0)+log1p(e^-|s|)
                ps += (s >= 0.0f) ? pa : 1.0f - pa;
            }
        }
        int tail = total & 3;
        if (sb == 0 && t < tail) {
            float s = scores[total - tail + t];
            float e = __expf(-fabsf(s));
            float pa = 1.0f / (1.0f + e);
            bce += fmaxf(s, 0.0f) - __logf(pa);
            ps += (s >= 0.0f) ? pa : 1.0f - pa;
        }
        __shared__ float r0[8], r1[8];
#pragma unroll
        for (int off = 16; off > 0; off >>= 1) {
            bce += __shfl_down_sync(0xFFFFFFFFu, bce, off);
            ps  += __shfl_down_sync(0xFFFFFFFFu, ps, off);
        }
        if (lane == 0) { r0[wid] = bce; r1[wid] = ps; }
        __syncthreads();
        if (t == 0) {
            float a = 0.0f, p = 0.0f;
            for (int w = 0; w < 8; w++) { a += r0[w]; p += r1[w]; }
            g_sacc[sb * 2 + 0] = a;
            g_sacc[sb * 2 + 1] = p;
        }
        return;
    }

    // ---------------- image role ----------------
    int b = blockIdx.x;
    __shared__ u64 s_key[MAX_G * TOPK];     // dedup key: (align_bits<<32)|(~g)
    __shared__ int s_anc[MAX_G * TOPK];
    __shared__ float s_val[MAX_G * TOPK * 8];
    __shared__ float s_acc[8];
    if (t < 8) s_acc[t] = 0.0f;

    const float4* pb_b = pred_boxes + (size_t)b * N;
    const float*  sc_b = scores + (size_t)b * N;

    int img = img_p[0];
    int n0 = img / 8, n1 = img / 16, n2 = img / 32;
    bool structured = (n0 * n0 + n1 * n1 + n2 * n2 == N) && img > 0;
    float imgf = fmaxf((float)img, 1.0f);
    float p0 = prompt[(size_t)b * P + 0], p1 = prompt[(size_t)b * P + 1];
    float pn = fmaxf(sqrtf(p0 * p0 + p1 * p1), 1e-12f);

    for (int gi = wid; gi < G; gi += 8) {
        float4 gt = gts[b * G + gi];
        u64 v[TOPK];
#pragma unroll
        for (int j = 0; j < TOPK; j++) v[j] = 0ULL;

        if (structured) {
            int nn0[3] = {n0, n1, n2};
            int bb0[3] = {0, n0 * n0, n0 * n0 + n1 * n1};
#pragma unroll
            for (int sc = 0; sc < 3; sc++) {
                float s = (float)(8 << sc);
                int n = nn0[sc];
                int cl = max((int)floorf(gt.x / s - 0.5f) - 1, 0);
                int ch = min((int)ceilf(gt.z / s - 0.5f) + 1, n - 1);
                int rl = max((int)floorf(gt.y / s - 0.5f) - 1, 0);
                int rh = min((int)ceilf(gt.w / s - 0.5f) + 1, n - 1);
                int cw = ch - cl + 1, rw = rh - rl + 1;
                if (cw <= 0 || rw <= 0) continue;
                int m = cw * rw;
                for (int k = lane; k < m; k += 32) {
                    int row = k / cw + rl;
                    int col = k - (k / cw) * cw + cl;
                    int a = bb0[sc] + row * n + col;
                    float2 an = anchors[a];
                    if (an.x >= gt.x && an.x <= gt.z && an.y >= gt.y && an.y <= gt.w) {
                        float4 pb = pb_b[a];
                        float iou = iou_fn(pb, gt);
                        float sv = sc_b[a];
                        float prob = 1.0f / (1.0f + __expf(-sv));
                        float i2 = iou * iou;
                        float align = prob * (i2 * i2 * i2);
                        u64 key = ((u64)__float_as_uint(align) << 32)
                                | (u64)(0xFFFFFFFFu - (unsigned)a);
                        if (key > v[TOPK - 1]) {
#pragma unroll
                            for (int j = 0; j < TOPK; j++)
                                if (key > v[j]) { u64 tv = v[j]; v[j] = key; key = tv; }
                        }
                    }
                }
            }
        } else {
            for (int a = lane; a < N; a += 32) {
                float2 an = anchors[a];
                if (an.x >= gt.x && an.x <= gt.z && an.y >= gt.y && an.y <= gt.w) {
                    float4 pb = pb_b[a];
                    float iou = iou_fn(pb, gt);
                    float sv = sc_b[a];
                    float prob = 1.0f / (1.0f + __expf(-sv));
                    float i2 = iou * iou;
                    float align = prob * (i2 * i2 * i2);
                    u64 key = ((u64)__float_as_uint(align) << 32)
                            | (u64)(0xFFFFFFFFu - (unsigned)a);
                    if (key > v[TOPK - 1]) {
#pragma unroll
                        for (int j = 0; j < TOPK; j++)
                            if (key > v[j]) { u64 tv = v[j]; v[j] = key; key = tv; }
                    }
                }
            }
        }

        // warp top-13 merge (keys unique): lane r receives winner r
        u64 myw = 0ULL;
        int ptr = 0;
        for (int r = 0; r < TOPK; r++) {
            u64 h = (ptr < TOPK) ? v[ptr] : 0ULL;
            int src = lane;
#pragma unroll
            for (int off = 16; off > 0; off >>= 1) {
                u64 o = __shfl_down_sync(0xFFFFFFFFu, h, off);
                int os = __shfl_down_sync(0xFFFFFFFFu, src, off);
                if (o > h) { h = o; src = os; }
            }
            u64 hb = __shfl_sync(0xFFFFFFFFu, h, 0);
            int sl = __shfl_sync(0xFFFFFFFFu, src, 0);
            if (hb == 0ULL) break;
            if (lane == sl) ptr++;
            if (lane == r) myw = hb;
        }

        if (lane < TOPK) {
            int slot = gi * TOPK + lane;
            if (myw == 0ULL) {
                s_key[slot] = 0ULL;
                s_anc[slot] = -1;
            } else {
                int a = (int)(0xFFFFFFFFu - (unsigned)(myw & 0xFFFFFFFFull));
                // dedup key: align bits high, then prefer LOWER g on ties
                s_key[slot] = (myw & 0xFFFFFFFF00000000ull)
                            | (u64)(0xFFFFFFFFu - (unsigned)gi);
                s_anc[slot] = a;
                // ---- heavy per-candidate loss terms (speculative) ----
                int idx = b * N + a;
                float4 pb = pb_b[a];
                float s = sc_b[a];
                float prob = 1.0f / (1.0f + __expf(-s));
                float iou = iou_fn(pb, gt);
                float ts = fmaxf(iou, 0.1f);
                float cw = fmaxf(pb.z, gt.z) - fminf(pb.x, gt.x);
                float ch = fmaxf(pb.w, gt.w) - fminf(pb.y, gt.y);
                float c2 = cw * cw + ch * ch + EPSF;
                float dx = gt.x + gt.z - pb.x - pb.z;
                float dy = gt.y + gt.w - pb.y - pb.w;
                float rho2 = (dx * dx + dy * dy) * 0.25f;
                float w1 = pb.z - pb.x, h1 = pb.w - pb.y + EPSF;
                float w2 = gt.z - gt.x, h2 = gt.w - gt.y + EPSF;
                float dat = atanf(w2 / h2) - atanf(w1 / h1);
                float vv = 0.40528473456935109f * dat * dat;
                float alpha = vv / (vv - iou + 1.0f + EPSF);
                float ciou = iou - rho2 / c2 - vv * alpha;
                float2 an = anchors[a];
                float st = strides[a];
                float dist[4];
                dist[0] = (an.x - gt.x) / st;
                dist[1] = (an.y - gt.y) / st;
                dist[2] = (gt.z - an.x) / st;
                dist[3] = (gt.w - an.y) / st;
                const float* lg = logits + (size_t)idx * 64;
                float dflv = 0.0f;
#pragma unroll
                for (int ch_i = 0; ch_i < 4; ch_i++) {
                    float x[16];
                    const float4* l4 = (const float4*)(lg + ch_i * 16);
#pragma unroll
                    for (int q = 0; q < 4; q++) {
                        float4 f = l4[q];
                        x[q * 4 + 0] = f.x; x[q * 4 + 1] = f.y;
                        x[q * 4 + 2] = f.z; x[q * 4 + 3] = f.w;
                    }
                    float m = x[0];
#pragma unroll
                    for (int q = 1; q < 16; q++) m = fmaxf(m, x[q]);
                    float se = 0.0f;
#pragma unroll
                    for (int q = 0; q < 16; q++) se += __expf(x[q] - m);
                    float logZ = m + __logf(se);
                    float d = fminf(fmaxf(dist[ch_i], 0.0f), 16.0f - 1.0f - 0.01f);
                    int tl = (int)d;
                    int tr = min(tl + 1, 15);
                    float wl = (float)tr - d;
                    float wr = 1.0f - wl;
                    dflv += (logZ - x[tl]) * wl + (logZ - x[tr]) * wr;
                }
                float cx = (gt.x + gt.z) * 0.5f / imgf;
                float cy = (gt.y + gt.w) * 0.5f / imgf;
                float cn = fmaxf(sqrtf(cx * cx + cy * cy), 1e-12f);
                cx /= cn; cy /= cn;
                float ctr = 1.0f - (cx * p0 + cy * p1) / pn;

                float* V = &s_val[slot * 8];
                V[0] = -s * ts;          // BCE correction
                V[1] = 1.0f;
                V[2] = prob;             // pos prob
                V[3] = 0.0f;
                V[4] = iou;              // matched iou
                V[5] = 1.0f - ciou;      // iou loss
                V[6] = dflv;             // dfl
                V[7] = ctr;              // contrast
            }
        }
    }
    __syncthreads();

    // ---- in-block dedup (argmax over gts per anchor) + accumulate ----
    int TS = G * TOPK;
    for (int j = t; j < TS; j += 256) {
        u64 kj = s_key[j];
        if (kj == 0ULL) continue;
        int aj = s_anc[j];
        bool win = true;
        for (int jj = 0; jj < TS; jj++) {
            if (s_anc[jj] == aj && s_key[jj] > kj) { win = false; break; }
        }
        if (win) {
            const float* V = &s_val[j * 8];
            atomicAdd(&s_acc[0], V[0]);
            atomicAdd(&s_acc[1], 1.0f);
            atomicAdd(&s_acc[2], V[2]);
            atomicAdd(&s_acc[4], V[4]);
            atomicAdd(&s_acc[5], V[5]);
            atomicAdd(&s_acc[6], V[6]);
            atomicAdd(&s_acc[7], V[7]);
        }
    }
    __syncthreads();
    if (t < 8) g_facc[b * 8 + t] = s_acc[t];   // plain store (stateless)
}

// Finalize: every block redundantly computes the identical 10 outputs
// from g_facc (B*8) and g_sacc (SCORE_BLOCKS*2). Pure reads; no state.
__global__ __launch_bounds__(64) void k_fin(float* __restrict__ out, int B, int N)
{
    int t = threadIdx.x;
    int lane = t & 31, wid = t >> 5;
    __shared__ float fa[MAX_B * 8];
    for (int i = t; i < B * 8; i += 64) fa[i] = g_facc[i];

    float bce = 0.0f, ps = 0.0f;
    for (int i = t; i < SCORE_BLOCKS; i += 64) {
        bce += g_sacc[2 * i + 0];
        ps  += g_sacc[2 * i + 1];
    }
    __shared__ float rb[2], rp[2];
#pragma unroll
    for (int off = 16; off > 0; off >>= 1) {
        bce += __shfl_down_sync(0xFFFFFFFFu, bce, off);
        ps  += __shfl_down_sync(0xFFFFFFFFu, ps, off);
    }
    if (lane == 0) { rb[wid] = bce; rp[wid] = ps; }
    __syncthreads();

    if (t == 0) {
        float bce0 = rb[0] + rb[1];
        float tot = rp[0] + rp[1];
        float corr = 0, iou = 0, dfl = 0, ctr = 0, tp = 0, pos = 0, mi = 0;
        for (int b = 0; b < B; b++) {
            const float* A = &fa[b * 8];
            float np = A[1];
            float rden = 1.0f / fmaxf(np, 1.0f);
            corr += A[0];
            tp += np;
            pos += A[2];
            mi += A[4];
            iou += A[5] * rden;
            dfl += A[6] * (0.25f * rden);
            ctr += A[7] * rden;
        }
        float match = (bce0 + corr) / (float)N;
        float nb_ = (float)B;
        float tneg = (float)B * (float)N - tp;
        out[0] = (1.0f * match + 7.5f * iou + 1.5f * dfl + 1.0f * ctr) / nb_;
        out[1] = match / nb_;
        out[2] = iou / nb_;
        out[3] = dfl / nb_;
        out[4] = ctr / nb_;
        out[5] = tp;
        out[6] = tneg;
        out[7] = pos / fmaxf(tp, 1.0f);
        out[8] = (tot - pos) / fmaxf(tneg, 1.0f);
        out[9] = mi / fmaxf(tp, 1.0f);
    }
}

extern "C" void kernel_launch(void* const* d_in, const int* in_sizes, int n_in,
                              void* d_out, int out_size) {
    const float* pred_boxes = (const float*)d_in[0];
    const float* pred_scores = (const float*)d_in[1];
    const float* anchors = (const float*)d_in[2];
    const float* strides = (const float*)d_in[3];
    const float* logits = (const float*)d_in[4];
    const float* prompt = (const float*)d_in[5];
    const float* gts = (const float*)d_in[6];
    const int* imgp = (const int*)d_in[7];

    int N = in_sizes[2] / 2;
    int B = in_sizes[1] / N;
    int G = in_sizes[6] / (4 * B);
    int P = in_sizes[5] / B;
    int total = B * N;

    k_main<<<B + SCORE_BLOCKS, 256>>>((const float4*)pred_boxes, pred_scores,
                                      (const float2*)anchors, strides, logits, prompt,
                                      (const float4*)gts, imgp,
                                      B, N, G, total, P);
    k_fin<<<FIN_BLOCKS, 64>>>((float*)d_out, B, N);
}

// round 17
// speedup vs baseline: 5.4281x; 5.4281x over previous
#include <cuda_runtime.h>
#include <math.h>

#define TOPK 13
#define EPSF 1e-7f
#define MAX_BN (1 << 20)
#define MAX_B 64
#define MAX_LIST 16384
#define SCORE_BLOCKS 124
#define FG_PER_BLOCK 32

typedef unsigned long long u64;

__device__ u64 g_key[MAX_BN];
__device__ double g_acc2[2];          // [0]=global bce0 sum, [1]=global prob sum (dense)
__device__ float g_facc[MAX_B * 8];   // per-image fg accumulators (fp32)
__device__ int g_cnt;
__device__ int g_done;
__device__ int2 g_list[MAX_LIST];
__device__ float g_vals[MAX_LIST * 8];

__device__ __forceinline__ float iou_fn(float4 a, float4 b) {
    float x1 = fmaxf(a.x, b.x), y1 = fmaxf(a.y, b.y);
    float x2 = fminf(a.z, b.z), y2 = fminf(a.w, b.w);
    float inter = fmaxf(x2 - x1, 0.0f) * fmaxf(y2 - y1, 0.0f);
    float aa = (a.z - a.x) * (a.w - a.y);
    float ab = (b.z - b.x) * (b.w - b.y);
    return inter / (aa + ab - inter + EPSF);
}

// Blocks [0, BG): assignment (one block per (image,gt)) + winner precompute.
// Blocks [BG, BG+SCORE_BLOCKS): dense score reduction (grid-stride).
__global__ __launch_bounds__(256) void k_main(
    const float4* __restrict__ pred_boxes, const float* __restrict__ scores,
    const float2* __restrict__ anchors, const float* __restrict__ strides,
    const float* __restrict__ logits, const float* __restrict__ prompt,
    const float4* __restrict__ gts, const int* __restrict__ img_p,
    int B, int N, int G, int BG, int total, int P)
{
    int t = threadIdx.x;
    int lane = t & 31, wid = t >> 5;

    if ((int)blockIdx.x >= BG) {
        // ---------------- score role (grid-stride) ----------------
        int sb = blockIdx.x - BG;
        int nv4 = total >> 2;
        float bce = 0.0f, ps = 0.0f;
        for (int i = sb * 256 + t; i < nv4; i += SCORE_BLOCKS * 256) {
            float4 s4 = ((const float4*)scores)[i];
            float sv[4] = {s4.x, s4.y, s4.z, s4.w};
#pragma unroll
            for (int j = 0; j < 4; j++) {
                float s = sv[j];
                float e = __expf(-fabsf(s));
                float pa = 1.0f / (1.0f + e);          // sigmoid(|s|)
                bce += fmaxf(s, 0.0f) - __logf(pa);    // max(s,0)+log1p(e^-|s|)
                ps += (s >= 0.0f) ? pa : 1.0f - pa;
            }
        }
        int tail = total & 3;
        if (sb == 0 && t < tail) {
            float s = scores[total - tail + t];
            float e = __expf(-fabsf(s));
            float pa = 1.0f / (1.0f + e);
            bce += fmaxf(s, 0.0f) - __logf(pa);
            ps += (s >= 0.0f) ? pa : 1.0f - pa;
        }
        __shared__ float r0[8], r1[8];
#pragma unroll
        for (int off = 16; off > 0; off >>= 1) {
            bce += __shfl_down_sync(0xFFFFFFFFu, bce, off);
            ps  += __shfl_down_sync(0xFFFFFFFFu, ps, off);
        }
        if (lane == 0) { r0[wid] = bce; r1[wid] = ps; }
        __syncthreads();
        if (t == 0) {
            float a = 0.0f, p = 0.0f;
            for (int w = 0; w < 8; w++) { a += r0[w]; p += r1[w]; }
            atomicAdd(&g_acc2[0], (double)a);
            atomicAdd(&g_acc2[1], (double)p);
        }
        return;
    }

    // ---------------- assign role ----------------
    int bg = blockIdx.x;
    int b = bg / G, g = bg % G;
    float4 gt = gts[bg];

    u64 v[TOPK];
#pragma unroll
    for (int j = 0; j < TOPK; j++) v[j] = 0ULL;

    const float4* pb_b = pred_boxes + (size_t)b * N;
    const float*  sc_b = scores + (size_t)b * N;

    int img = img_p[0];
    int n0 = img / 8, n1 = img / 16, n2 = img / 32;
    bool structured = (n0 * n0 + n1 * n1 + n2 * n2 == N) && img > 0;

    if (structured) {
        int nn[3] = {n0, n1, n2};
        int base[3] = {0, n0 * n0, n0 * n0 + n1 * n1};
        int c0[3], r0a[3], cw[3], m[3];
        int M = 0;
#pragma unroll
        for (int sc = 0; sc < 3; sc++) {
            float s = (float)(8 << sc);
            int n = nn[sc];
            int cl = max((int)floorf(gt.x / s - 0.5f) - 1, 0);
            int ch = min((int)ceilf(gt.z / s - 0.5f) + 1, n - 1);
            int rl = max((int)floorf(gt.y / s - 0.5f) - 1, 0);
            int rh = min((int)ceilf(gt.w / s - 0.5f) + 1, n - 1);
            int ccw = ch - cl + 1, crh = rh - rl + 1;
            if (ccw < 0) ccw = 0;
            if (crh < 0) crh = 0;
            c0[sc] = cl; r0a[sc] = rl; cw[sc] = ccw;
            m[sc] = ccw * crh;
            M += m[sc];
        }
        for (int k = t; k < M; k += 256) {
            int sc = 0, rel = k;
            while (rel >= m[sc]) { rel -= m[sc]; sc++; }
            int row = rel / cw[sc] + r0a[sc];
            int col = rel - (rel / cw[sc]) * cw[sc] + c0[sc];
            int a = base[sc] + row * nn[sc] + col;
            float2 an = anchors[a];
            if (an.x >= gt.x && an.x <= gt.z && an.y >= gt.y && an.y <= gt.w) {
                float4 pb = pb_b[a];
                float iou = iou_fn(pb, gt);
                float s = sc_b[a];
                float prob = 1.0f / (1.0f + __expf(-s));
                float i2 = iou * iou;
                float align = prob * (i2 * i2 * i2);
                u64 key = ((u64)__float_as_uint(align) << 32)
                        | (u64)(0xFFFFFFFFu - (unsigned)a);
                if (key > v[TOPK - 1]) {
#pragma unroll
                    for (int j = 0; j < TOPK; j++)
                        if (key > v[j]) { u64 tv = v[j]; v[j] = key; key = tv; }
                }
            }
        }
    } else {
        for (int a = t; a < N; a += 256) {
            float2 an = anchors[a];
            if (an.x >= gt.x && an.x <= gt.z && an.y >= gt.y && an.y <= gt.w) {
                float4 pb = pb_b[a];
                float iou = iou_fn(pb, gt);
                float s = sc_b[a];
                float prob = 1.0f / (1.0f + __expf(-s));
                float i2 = iou * iou;
                float align = prob * (i2 * i2 * i2);
                u64 key = ((u64)__float_as_uint(align) << 32)
                        | (u64)(0xFFFFFFFFu - (unsigned)a);
                if (key > v[TOPK - 1]) {
#pragma unroll
                    for (int j = 0; j < TOPK; j++)
                        if (key > v[j]) { u64 tv = v[j]; v[j] = key; key = tv; }
                }
            }
        }
    }

    // ---- level 1: per-warp top-13 ----
    __shared__ u64 s_all[8 * TOPK];
    {
        u64 myw = 0ULL;
        int ptr = 0;
        for (int r = 0; r < TOPK; r++) {
            u64 h = (ptr < TOPK) ? v[ptr] : 0ULL;
            int src = lane;
#pragma unroll
            for (int off = 16; off > 0; off >>= 1) {
                u64 o = __shfl_down_sync(0xFFFFFFFFu, h, off);
                int os = __shfl_down_sync(0xFFFFFFFFu, src, off);
                if (o > h) { h = o; src = os; }
            }
            u64 hb = __shfl_sync(0xFFFFFFFFu, h, 0);
            int sl = __shfl_sync(0xFFFFFFFFu, src, 0);
            if (hb == 0ULL) break;
            if (lane == sl) ptr++;
            if (lane == r) myw = hb;
        }
        if (lane < TOPK) s_all[wid * TOPK + lane] = myw;   // sorted desc
    }
    __syncthreads();
    if (wid != 0) return;   // keeps scan & precompute in separate reg regions

    // ---- level 2: warp 0 merges 8 sorted lists ----
    u64 myw = 0ULL;
    {
        int ptr = 0;
        for (int r = 0; r < TOPK; r++) {
            u64 h = (lane < 8 && ptr < TOPK) ? s_all[lane * TOPK + ptr] : 0ULL;
            int src = lane;
#pragma unroll
            for (int off = 4; off > 0; off >>= 1) {
                u64 o = __shfl_down_sync(0xFFFFFFFFu, h, off);
                int os = __shfl_down_sync(0xFFFFFFFFu, src, off);
                if (o > h) { h = o; src = os; }
            }
            u64 hb = __shfl_sync(0xFFFFFFFFu, h, 0);
            int sl = __shfl_sync(0xFFFFFFFFu, src, 0);
            if (hb == 0ULL) break;
            if (lane == sl) ptr++;
            if (lane == r) myw = hb;
        }
    }

    // ---- winner lanes: scatter key + speculative loss precompute ----
    if (lane < TOPK && myw != 0ULL) {
        unsigned bits = (unsigned)(myw >> 32);
        int a = (int)(0xFFFFFFFFu - (unsigned)(myw & 0xFFFFFFFFull));
        int idx = b * N + a;
        u64 key = ((u64)(bits + 1u) << 32) | (u64)(0xFFFFFFFFu - (unsigned)g);
        atomicMax(&g_key[idx], key);
        int pos = atomicAdd(&g_cnt, 1);
        if (pos < MAX_LIST) {
            g_list[pos] = make_int2(idx, g);
            float4 pb = pb_b[a];
            float s = sc_b[a];
            float prob = 1.0f / (1.0f + __expf(-s));
            float iou = iou_fn(pb, gt);
            float ts = fmaxf(iou, 0.1f);
            float cw = fmaxf(pb.z, gt.z) - fminf(pb.x, gt.x);
            float ch = fmaxf(pb.w, gt.w) - fminf(pb.y, gt.y);
            float c2 = cw * cw + ch * ch + EPSF;
            float dx = gt.x + gt.z - pb.x - pb.z;
            float dy = gt.y + gt.w - pb.y - pb.w;
            float rho2 = (dx * dx + dy * dy) * 0.25f;
            float w1 = pb.z - pb.x, h1 = pb.w - pb.y + EPSF;
            float w2 = gt.z - gt.x, h2 = gt.w - gt.y + EPSF;
            float dat = atanf(w2 / h2) - atanf(w1 / h1);
            float vv = 0.40528473456935109f * dat * dat;
            float alpha = vv / (vv - iou + 1.0f + EPSF);
            float ciou = iou - rho2 / c2 - vv * alpha;
            float2 an = anchors[a];
            float st = strides[a];
            float dist[4];
            dist[0] = (an.x - gt.x) / st;
            dist[1] = (an.y - gt.y) / st;
            dist[2] = (gt.z - an.x) / st;
            dist[3] = (gt.w - an.y) / st;
            const float* lg = logits + (size_t)idx * 64;
            float dflv = 0.0f;
#pragma unroll
            for (int ch_i = 0; ch_i < 4; ch_i++) {
                float x[16];
                const float4* l4 = (const float4*)(lg + ch_i * 16);
#pragma unroll
                for (int q = 0; q < 4; q++) {
                    float4 f = l4[q];
                    x[q * 4 + 0] = f.x; x[q * 4 + 1] = f.y;
                    x[q * 4 + 2] = f.z; x[q * 4 + 3] = f.w;
                }
                float m = x[0];
#pragma unroll
                for (int q = 1; q < 16; q++) m = fmaxf(m, x[q]);
                float se = 0.0f;
#pragma unroll
                for (int q = 0; q < 16; q++) se += __expf(x[q] - m);
                float logZ = m + __logf(se);
                float d = fminf(fmaxf(dist[ch_i], 0.0f), 16.0f - 1.0f - 0.01f);
                int tl = (int)d;
                int tr = min(tl + 1, 15);
                float wl = (float)tr - d;
                float wr = 1.0f - wl;
                dflv += (logZ - x[tl]) * wl + (logZ - x[tr]) * wr;
            }
            float imgf = fmaxf((float)img, 1.0f);
            float cx = (gt.x + gt.z) * 0.5f / imgf;
            float cy = (gt.y + gt.w) * 0.5f / imgf;
            float cn = fmaxf(sqrtf(cx * cx + cy * cy), 1e-12f);
            cx /= cn; cy /= cn;
            float p0 = prompt[(size_t)b * P + 0], p1 = prompt[(size_t)b * P + 1];
            float pn = fmaxf(sqrtf(p0 * p0 + p1 * p1), 1e-12f);
            float ctr = 1.0f - (cx * p0 + cy * p1) / pn;

            float* V = g_vals + (size_t)pos * 8;
            V[0] = -s * ts;          // BCE correction
            V[1] = 1.0f;
            V[2] = prob;             // pos prob
            V[3] = 0.0f;
            V[4] = iou;              // matched iou
            V[5] = 1.0f - ciou;      // iou loss
            V[6] = dflv;             // dfl
            V[7] = ctr;              // contrast
        }
    }
}

// Winner check + fp32 accumulate; 64-thread blocks, 32 entries each.
// PDL: grid-dependency sync at top; values prefetched alongside key.
// Last block finalizes (fp32).
__global__ __launch_bounds__(64) void k_fg(
    float* __restrict__ out, int B, int N)
{
#if __CUDA_ARCH__ >= 900
    cudaGridDependencySynchronize();
#endif
    __shared__ float acc_s[MAX_B * 8];
    int t = threadIdx.x;
    for (int i = t; i < B * 8; i += 64) acc_s[i] = 0.0f;
    __syncthreads();

    int i = blockIdx.x * FG_PER_BLOCK + t;
    int cnt = g_cnt;
    if (cnt > MAX_LIST) cnt = MAX_LIST;
    if (t < FG_PER_BLOCK && i < cnt) {
        int2 e = g_list[i];
        int idx = e.x, g = e.y;
        // prefetch values in parallel with the key load
        const float* Vp = g_vals + (size_t)i * 8;
        float4 v0 = *(const float4*)Vp;
        float4 v1 = *(const float4*)(Vp + 4);
        u64 key = g_key[idx];
        int gw = (int)(0xFFFFFFFFu - (unsigned)(key & 0xFFFFFFFFull));
        if (key != 0ULL && gw == g) {
            g_key[idx] = 0ULL;    // exactly-once cleanup by the winner
            int b = idx / N;
            float* A = acc_s + b * 8;
            atomicAdd(&A[0], v0.x);
            atomicAdd(&A[1], 1.0f);
            atomicAdd(&A[2], v0.z);
            atomicAdd(&A[4], v1.x);
            atomicAdd(&A[5], v1.y);
            atomicAdd(&A[6], v1.z);
            atomicAdd(&A[7], v1.w);
        }
    }
    __syncthreads();
    for (int j = t; j < B * 8; j += 64) {
        float val = acc_s[j];
        if (val != 0.0f) atomicAdd(&g_facc[j], val);
    }
    __syncthreads();

    __shared__ int s_last;
    if (t == 0) {
        __threadfence();                    // one fence per block
        s_last = (atomicAdd(&g_done, 1) == (int)gridDim.x - 1);
    }
    __syncthreads();
    if (!s_last) return;
    if (t == 0) __threadfence();
    __syncthreads();

    // ---- last block: finalize (fp32) + reset ----
    __shared__ float pm[MAX_B], pi[MAX_B], pdf[MAX_B], pc[MAX_B];
    __shared__ float pt[MAX_B], pp[MAX_B], pmi[MAX_B];
    if (t < B) {
        const float* A = &g_facc[t * 8];
        float np = A[1];
        float den = fmaxf(np, 1.0f);
        float rden = 1.0f / den;
        pm[t] = A[0];                 // bce correction (sum; /N later)
        pt[t] = np;
        pp[t] = A[2];
        pmi[t] = A[4];
        pi[t] = A[5] * rden;
        pdf[t] = A[6] * (0.25f * rden);
        pc[t] = A[7] * rden;
    }
    __syncthreads();
    if (t == 0) {
        float corr = 0, iou = 0, dfl = 0, ctr = 0, tp = 0, pos = 0, mi = 0;
        for (int b = 0; b < B; b++) {
            corr += pm[b]; iou += pi[b]; dfl += pdf[b]; ctr += pc[b];
            tp += pt[b]; pos += pp[b]; mi += pmi[b];
        }
        float bce0 = (float)g_acc2[0];
        float tot = (float)g_acc2[1];
        float match = (bce0 + corr) / (float)N;
        float nb_ = (float)B;
        float tneg = (float)B * (float)N - tp;
        out[0] = (1.0f * match + 7.5f * iou + 1.5f * dfl + 1.0f * ctr) / nb_;
        out[1] = match / nb_;
        out[2] = iou / nb_;
        out[3] = dfl / nb_;
        out[4] = ctr / nb_;
        out[5] = tp;
        out[6] = tneg;
        out[7] = pos / fmaxf(tp, 1.0f);
        out[8] = (tot - pos) / fmaxf(tneg, 1.0f);
        out[9] = mi / fmaxf(tp, 1.0f);
        g_cnt = 0;
        g_done = 0;
        g_acc2[0] = 0.0;
        g_acc2[1] = 0.0;
    }
    __syncthreads();
    for (int j = t; j < B * 8; j += 64) g_facc[j] = 0.0f;
}

extern "C" void kernel_launch(void* const* d_in, const int* in_sizes, int n_in,
                              void* d_out, int out_size) {
    const float* pred_boxes = (const float*)d_in[0];
    const float* pred_scores = (const float*)d_in[1];
    const float* anchors = (const float*)d_in[2];
    const float* strides = (const float*)d_in[3];
    const float* logits = (const float*)d_in[4];
    const float* prompt = (const float*)d_in[5];
    const float* gts = (const float*)d_in[6];
    const int* imgp = (const int*)d_in[7];

    int N = in_sizes[2] / 2;
    int B = in_sizes[1] / N;
    int G = in_sizes[6] / (4 * B);
    int P = in_sizes[5] / B;
    int BG = B * G;
    int total = B * N;

    k_main<<<BG + SCORE_BLOCKS, 256>>>((const float4*)pred_boxes, pred_scores,
                                       (const float2*)anchors, strides, logits, prompt,
                                       (const float4*)gts, imgp,
                                       B, N, G, BG, total, P);
    int cap = BG * TOPK;
    if (cap > MAX_LIST) cap = MAX_LIST;
    int fgBlocks = (cap + FG_PER_BLOCK - 1) / FG_PER_BLOCK;

    // PDL launch: overlap k_fg's launch latency with k_main's epilogue.
    cudaLaunchConfig_t cfg = {};
    cfg.gridDim = dim3((unsigned)fgBlocks);
    cfg.blockDim = dim3(64);
    cudaLaunchAttribute attr[1];
    attr[0].id = cudaLaunchAttributeProgrammaticStreamSerialization;
    attr[0].val.programmaticStreamSerializationAllowed = 1;
    cfg.attrs = attr;
    cfg.numAttrs = 1;
    cudaLaunchKernelEx(&cfg, k_fg, (float*)d_out, B, N);
}